// round 1
// baseline (speedup 1.0000x reference)
#include <cuda_runtime.h>
#include <math.h>

// Problem constants
#define BTN   64          // B*T
#define SEQ   264         // tokens per (b,t)
#define MROWS (BTN*SEQ)   // 16896
#define GDIM  1024        // model dim (= K of all GEMMs)
#define NH    16
#define NKV   4
#define HD    64
#define QKV_N 1536        // 1024 q + 256 k + 256 v
#define NZ    256         // latent tokens with RoPE
#define SPATIAL 16

// Scratch (static device allocations — no cudaMalloc allowed)
__device__ float g_w[QKV_N * GDIM];                      // packed [wq;wk;wv]
__device__ float g_qkv[(size_t)MROWS * QKV_N];           // qkv projections
__device__ float g_attn[(size_t)MROWS * GDIM];           // attention output

// ---------------------------------------------------------------------------
// Pack wq/wk/wv into one (1536 x 1024) row-major weight buffer
// ---------------------------------------------------------------------------
__global__ void pack_w_kernel(const float* __restrict__ wq,
                              const float* __restrict__ wk,
                              const float* __restrict__ wv) {
    int total = QKV_N * GDIM;
    for (int i = blockIdx.x * blockDim.x + threadIdx.x; i < total;
         i += gridDim.x * blockDim.x) {
        int n = i / GDIM, k = i - n * GDIM;
        float v;
        if (n < NH * HD)            v = wq[n * GDIM + k];
        else if (n < NH*HD + NKV*HD) v = wk[(n - NH*HD) * GDIM + k];
        else                         v = wv[(n - NH*HD - NKV*HD) * GDIM + k];
        g_w[i] = v;
    }
}

// ---------------------------------------------------------------------------
// SGEMM: C[m][n] = sum_k A[m][k] * B[n][k]   (A: Mx1024, B: Nx1024 row-major)
// 128x128 tile, BK=16, 8x8 per thread, 256 threads. M,N multiples of 128.
// ---------------------------------------------------------------------------
__global__ __launch_bounds__(256, 2)
void sgemm_tn(const float* __restrict__ A, const float* __restrict__ B,
              float* __restrict__ C, int ldc) {
    const int BK = 16;
    __shared__ __align__(16) float As[BK][132];
    __shared__ __align__(16) float Bs[BK][132];

    int tid = threadIdx.x;
    int tx = tid & 15;        // n-dir (0..15)
    int ty = tid >> 4;        // m-dir (0..15)
    int bm = blockIdx.y * 128;
    int bn = blockIdx.x * 128;

    const float* Ab = A + (size_t)bm * GDIM;
    const float* Bb = B + (size_t)bn * GDIM;

    float acc[8][8];
#pragma unroll
    for (int i = 0; i < 8; i++)
#pragma unroll
        for (int j = 0; j < 8; j++) acc[i][j] = 0.f;

    for (int k0 = 0; k0 < GDIM; k0 += BK) {
        // 128x16 tiles: 512 float4 per operand, 2 per thread
#pragma unroll
        for (int l = 0; l < 2; l++) {
            int idx = tid + l * 256;
            int row = idx >> 2;
            int kq = (idx & 3) << 2;
            float4 va = *(const float4*)(Ab + (size_t)row * GDIM + k0 + kq);
            As[kq + 0][row] = va.x; As[kq + 1][row] = va.y;
            As[kq + 2][row] = va.z; As[kq + 3][row] = va.w;
            float4 vb = *(const float4*)(Bb + (size_t)row * GDIM + k0 + kq);
            Bs[kq + 0][row] = vb.x; Bs[kq + 1][row] = vb.y;
            Bs[kq + 2][row] = vb.z; Bs[kq + 3][row] = vb.w;
        }
        __syncthreads();
#pragma unroll
        for (int kk = 0; kk < BK; kk++) {
            float a[8], b[8];
#pragma unroll
            for (int i = 0; i < 8; i++) a[i] = As[kk][ty * 8 + i];
#pragma unroll
            for (int j = 0; j < 8; j++) b[j] = Bs[kk][tx * 8 + j];
#pragma unroll
            for (int i = 0; i < 8; i++)
#pragma unroll
                for (int j = 0; j < 8; j++) acc[i][j] += a[i] * b[j];
        }
        __syncthreads();
    }

#pragma unroll
    for (int i = 0; i < 8; i++) {
        size_t r = (size_t)(bm + ty * 8 + i) * ldc + bn + tx * 8;
#pragma unroll
        for (int j = 0; j < 8; j += 4) {
            float4 v = make_float4(acc[i][j], acc[i][j+1], acc[i][j+2], acc[i][j+3]);
            *(float4*)(C + r + j) = v;
        }
    }
}

// ---------------------------------------------------------------------------
// QKNorm (RMSNorm over HD) + partial 2D RoPE on first NZ tokens, in-place.
// grid: (20 head-slots, 16896 rows), block: 64 threads (one vector)
// ---------------------------------------------------------------------------
__global__ void norm_rope_kernel(const float* __restrict__ qw,
                                 const float* __restrict__ kw) {
    int hh = blockIdx.x;       // 0..15: q heads; 16..19: k heads
    int row = blockIdx.y;      // 0..16895
    int d = threadIdx.x;       // 0..63
    bool is_q = hh < NH;
    int col = is_q ? hh * HD + d : GDIM + (hh - NH) * HD + d;
    float* ptr = g_qkv + (size_t)row * QKV_N + col;
    float v = *ptr;

    // sum of squares over 64 lanes (2 warps)
    __shared__ float red[2];
    float sq = v * v;
#pragma unroll
    for (int o = 16; o; o >>= 1) sq += __shfl_xor_sync(0xffffffffu, sq, o);
    if ((d & 31) == 0) red[d >> 5] = sq;
    __syncthreads();
    float mean = (red[0] + red[1]) * (1.0f / HD);
    float w = is_q ? qw[d] : kw[d];
    v = v * rsqrtf(mean + 1e-6f) * w;

    int s = row % SEQ;
    __shared__ float vals[64];
    if (s < NZ) {
        vals[d] = v;
        __syncthreads();
        int half = d & 31;
        int j = half & 15;
        float pos = (half < 16) ? (float)(s >> 4) : (float)(s & 15);
        // inv_freq = 10000^(-j/16) = exp(-j * ln(10000)/16)
        float invf = __expf(-(float)j * 0.57564627324851142f);
        float ang = pos * invf;
        float c, sn;
        sincosf(ang, &sn, &c);
        float rot = (d < 32) ? -vals[d + 32] : vals[d - 32];
        v = v * c + rot * sn;
    }
    *ptr = v;
}

// ---------------------------------------------------------------------------
// Attention: one block per (bt, head). K and V tiles resident in smem.
// Per-thread streaming softmax (softcap bounds |s|<=50 => no overflow, no max).
// ---------------------------------------------------------------------------
__global__ void __launch_bounds__(288, 1) attn_kernel() {
    int h  = blockIdx.x;   // 0..15
    int bt = blockIdx.y;   // 0..63
    extern __shared__ __align__(16) float sm[];
    float* Ks = sm;                 // SEQ*HD
    float* Vs = sm + SEQ * HD;      // SEQ*HD
    int tid = threadIdx.x;
    int kvh = h >> 2;               // GROUPS = 4
    const float* base = g_qkv + (size_t)bt * SEQ * QKV_N;
    int kcol = GDIM + kvh * HD;
    int vcol = GDIM + NKV * HD + kvh * HD;

    for (int f = tid; f < SEQ * HD / 4; f += blockDim.x) {
        int j = f >> 4;
        int d4 = (f & 15) << 2;
        *(float4*)(Ks + j * HD + d4) =
            *(const float4*)(base + (size_t)j * QKV_N + kcol + d4);
        *(float4*)(Vs + j * HD + d4) =
            *(const float4*)(base + (size_t)j * QKV_N + vcol + d4);
    }
    __syncthreads();

    if (tid >= SEQ) return;
    size_t row = (size_t)bt * SEQ + tid;
    const float* qp = g_qkv + row * QKV_N + h * HD;
    float4 q[16];
#pragma unroll
    for (int i = 0; i < 16; i++) q[i] = *(const float4*)(qp + i * 4);

    float4 acc[16];
#pragma unroll
    for (int i = 0; i < 16; i++) acc[i] = make_float4(0.f, 0.f, 0.f, 0.f);
    float l = 0.f;

    for (int j = 0; j < SEQ; j++) {
        const float4* kr = (const float4*)(Ks + j * HD);
        float s0 = 0.f, s1 = 0.f, s2 = 0.f, s3 = 0.f;
#pragma unroll
        for (int i = 0; i < 16; i++) {
            float4 kv = kr[i];
            s0 += q[i].x * kv.x; s1 += q[i].y * kv.y;
            s2 += q[i].z * kv.z; s3 += q[i].w * kv.w;
        }
        float s = ((s0 + s1) + (s2 + s3)) * 0.125f;     // * HD^-0.5
        s = 50.0f * tanhf(s * 0.02f);                   // soft cap
        float p = __expf(s);
        l += p;
        const float4* vr = (const float4*)(Vs + j * HD);
#pragma unroll
        for (int i = 0; i < 16; i++) {
            float4 vv = vr[i];
            acc[i].x += p * vv.x; acc[i].y += p * vv.y;
            acc[i].z += p * vv.z; acc[i].w += p * vv.w;
        }
    }

    float inv = 1.0f / l;
    float* op = g_attn + row * GDIM + h * HD;
#pragma unroll
    for (int i = 0; i < 16; i++) {
        float4 o = acc[i];
        o.x *= inv; o.y *= inv; o.z *= inv; o.w *= inv;
        *(float4*)(op + i * 4) = o;
    }
}

// ---------------------------------------------------------------------------
extern "C" void kernel_launch(void* const* d_in, const int* in_sizes, int n_in,
                              void* d_out, int out_size) {
    const float* x   = (const float*)d_in[0];
    const float* wq  = (const float*)d_in[1];
    const float* wk  = (const float*)d_in[2];
    const float* wv  = (const float*)d_in[3];
    const float* wo  = (const float*)d_in[4];
    const float* qnw = (const float*)d_in[5];
    const float* knw = (const float*)d_in[6];
    float* out = (float*)d_out;

    float *wbuf, *qkvbuf, *attnbuf;
    cudaGetSymbolAddress((void**)&wbuf, g_w);
    cudaGetSymbolAddress((void**)&qkvbuf, g_qkv);
    cudaGetSymbolAddress((void**)&attnbuf, g_attn);

    const int attn_smem = 2 * SEQ * HD * (int)sizeof(float);  // 135168
    cudaFuncSetAttribute((const void*)attn_kernel,
                         cudaFuncAttributeMaxDynamicSharedMemorySize, attn_smem);

    // 1) pack weights, QKV projection
    pack_w_kernel<<<256, 256>>>(wq, wk, wv);
    sgemm_tn<<<dim3(QKV_N / 128, MROWS / 128), 256>>>(x, wbuf, qkvbuf, QKV_N);

    // 2) QKNorm + 2D RoPE in place
    norm_rope_kernel<<<dim3(NH + NKV, MROWS), 64>>>(qnw, knw);

    // 3) attention
    attn_kernel<<<dim3(NH, BTN), 288, attn_smem>>>();

    // 4) output projection straight into d_out
    sgemm_tn<<<dim3(GDIM / 128, MROWS / 128), 256>>>(attnbuf, wo, out, GDIM);
}

// round 3
// speedup vs baseline: 1.8316x; 1.8316x over previous
#include <cuda_runtime.h>
#include <cuda_bf16.h>
#include <stdint.h>
#include <math.h>

// Problem constants
#define BTN   64
#define SEQ   264
#define MROWS (BTN*SEQ)      // 16896
#define GDIM  1024
#define NH    16
#define NKV   4
#define HD    64
#define QKV_N 1536
#define NZ    256

// GEMM tiling
#define BK    32
#define KT    (GDIM/BK)      // 32 k-chunks
#define NSTG  3
#define STAGE_B 32768        // A(hi,lo)=16K + B(hi,lo)=16K
#define PLANE_B 8192         // 128 rows x 32 bf16 = 8KB per plane
#define GEMM_SMEM (NSTG*STAGE_B)   // 98304

// ---------------------------------------------------------------------------
// device scratch (static; no cudaMalloc allowed)
// ---------------------------------------------------------------------------
__device__ __align__(16) __nv_bfloat16 g_xhi[(size_t)MROWS * GDIM];
__device__ __align__(16) __nv_bfloat16 g_xlo[(size_t)MROWS * GDIM];
__device__ __align__(16) __nv_bfloat16 g_whi[(size_t)QKV_N * GDIM];
__device__ __align__(16) __nv_bfloat16 g_wlo[(size_t)QKV_N * GDIM];
__device__ __align__(16) __nv_bfloat16 g_wohi[(size_t)GDIM * GDIM];
__device__ __align__(16) __nv_bfloat16 g_wolo[(size_t)GDIM * GDIM];
__device__ __align__(16) __nv_bfloat16 g_ahi[(size_t)MROWS * GDIM];
__device__ __align__(16) __nv_bfloat16 g_alo[(size_t)MROWS * GDIM];
__device__ __align__(16) float         g_qkv[(size_t)MROWS * QKV_N];

// ---------------------------------------------------------------------------
// helpers
// ---------------------------------------------------------------------------
__device__ __forceinline__ uint32_t smem_u32(const void* p) {
    uint32_t a;
    asm("{ .reg .u64 t; cvta.to.shared.u64 t, %1; cvt.u32.u64 %0, t; }"
        : "=r"(a) : "l"(p));
    return a;
}
__device__ __forceinline__ void cp16(uint32_t dst, const void* src) {
    asm volatile("cp.async.cg.shared.global [%0], [%1], 16;"
                 :: "r"(dst), "l"(src));
}
#define CP_COMMIT() asm volatile("cp.async.commit_group;" ::: "memory")
#define CP_WAIT(n)  asm volatile("cp.async.wait_group %0;" :: "n"(n) : "memory")

__device__ __forceinline__ void ldsm4(uint32_t* r, uint32_t addr) {
    asm volatile("ldmatrix.sync.aligned.m8n8.x4.shared.b16 {%0,%1,%2,%3}, [%4];"
                 : "=r"(r[0]), "=r"(r[1]), "=r"(r[2]), "=r"(r[3]) : "r"(addr));
}
__device__ __forceinline__ void mma16816(float* c, const uint32_t* a, const uint32_t* b) {
    asm volatile(
        "mma.sync.aligned.m16n8k16.row.col.f32.bf16.bf16.f32 "
        "{%0,%1,%2,%3}, {%4,%5,%6,%7}, {%8,%9}, {%0,%1,%2,%3};"
        : "+f"(c[0]), "+f"(c[1]), "+f"(c[2]), "+f"(c[3])
        : "r"(a[0]), "r"(a[1]), "r"(a[2]), "r"(a[3]), "r"(b[0]), "r"(b[1]));
}

// swizzled byte offset of 16B unit (r, u) within a 128x32 bf16 plane
__device__ __forceinline__ uint32_t swz(int r, int u) {
    return (uint32_t)(r * 64 + ((u ^ ((r >> 1) & 3)) << 4));
}

// ---------------------------------------------------------------------------
// split fp32 -> (hi, lo) bf16, row-major
// ---------------------------------------------------------------------------
__device__ __forceinline__ void split8(const float* __restrict__ s, uint4& hv, uint4& lv) {
    float4 f0 = *(const float4*)s;
    float4 f1 = *(const float4*)(s + 4);
    float f[8] = {f0.x, f0.y, f0.z, f0.w, f1.x, f1.y, f1.z, f1.w};
    uint16_t hb[8], lb[8];
#pragma unroll
    for (int j = 0; j < 8; j++) {
        __nv_bfloat16 h = __float2bfloat16(f[j]);
        float r = f[j] - __bfloat162float(h);
        hb[j] = __bfloat16_as_ushort(h);
        lb[j] = __bfloat16_as_ushort(__float2bfloat16(r));
    }
    hv.x = hb[0] | ((uint32_t)hb[1] << 16); hv.y = hb[2] | ((uint32_t)hb[3] << 16);
    hv.z = hb[4] | ((uint32_t)hb[5] << 16); hv.w = hb[6] | ((uint32_t)hb[7] << 16);
    lv.x = lb[0] | ((uint32_t)lb[1] << 16); lv.y = lb[2] | ((uint32_t)lb[3] << 16);
    lv.z = lb[4] | ((uint32_t)lb[5] << 16); lv.w = lb[6] | ((uint32_t)lb[7] << 16);
}

__global__ void split_rm(const float* __restrict__ src, __nv_bfloat16* __restrict__ hi,
                         __nv_bfloat16* __restrict__ lo, int nunits) {
    for (int i = blockIdx.x * blockDim.x + threadIdx.x; i < nunits;
         i += gridDim.x * blockDim.x) {
        uint4 hv, lv;
        split8(src + (size_t)i * 8, hv, lv);
        ((uint4*)hi)[i] = hv;
        ((uint4*)lo)[i] = lv;
    }
}

__global__ void split_w_qkv(const float* __restrict__ wq, const float* __restrict__ wk,
                            const float* __restrict__ wv) {
    int nunits = QKV_N * (GDIM / 8);
    for (int i = blockIdx.x * blockDim.x + threadIdx.x; i < nunits;
         i += gridDim.x * blockDim.x) {
        int row = i >> 7, ur = i & 127;
        const float* srow;
        if (row < NH * HD)                srow = wq + (size_t)row * GDIM;
        else if (row < NH*HD + NKV*HD)    srow = wk + (size_t)(row - NH*HD) * GDIM;
        else                              srow = wv + (size_t)(row - NH*HD - NKV*HD) * GDIM;
        uint4 hv, lv;
        split8(srow + ur * 8, hv, lv);
        ((uint4*)g_whi)[i] = hv;
        ((uint4*)g_wlo)[i] = lv;
    }
}

// ---------------------------------------------------------------------------
// bf16x3 GEMM via mma.sync: out[m][n] = sum_k A[m][k]*B[n][k], K=1024
// block 128x128, BK=32, 8 warps (warptile 64x32), 3-stage cp.async pipeline
// ---------------------------------------------------------------------------
__device__ __forceinline__ void load_stage(uint32_t sb, int stage,
        const __nv_bfloat16* __restrict__ Ah, const __nv_bfloat16* __restrict__ Al,
        const __nv_bfloat16* __restrict__ Bh, const __nv_bfloat16* __restrict__ Bl,
        int bm, int bn, int kc, int tid) {
    uint32_t st = sb + stage * STAGE_B;
#pragma unroll
    for (int i = 0; i < 8; i++) {
        int v = i * 256 + tid;
        int op = v >> 9;          // 0:Ah 1:Al 2:Bh 3:Bl
        int w = v & 511;
        int r = w >> 2, u = w & 3;
        const __nv_bfloat16* base = (op == 0) ? Ah : (op == 1) ? Al : (op == 2) ? Bh : Bl;
        int grow = ((op < 2) ? bm : bn) * 128 + r;
        const __nv_bfloat16* g = base + (size_t)grow * GDIM + kc * BK + u * 8;
        cp16(st + op * PLANE_B + swz(r, u), g);
    }
}

__global__ __launch_bounds__(256, 1)
void gemm_mma(const __nv_bfloat16* __restrict__ Ah, const __nv_bfloat16* __restrict__ Al,
              const __nv_bfloat16* __restrict__ Bh, const __nv_bfloat16* __restrict__ Bl,
              float* __restrict__ out, int ldc) {
    extern __shared__ __align__(1024) char smem[];
    uint32_t sb = smem_u32(smem);
    int tid = threadIdx.x, wid = tid >> 5, lane = tid & 31;
    int bm = blockIdx.y, bn = blockIdx.x;
    int wm = wid >> 2;        // 0..1 -> m offset wm*64
    int wn = wid & 3;         // 0..3 -> n offset wn*32

    float acc[4][4][4];
#pragma unroll
    for (int a = 0; a < 4; a++)
#pragma unroll
        for (int b = 0; b < 4; b++)
#pragma unroll
            for (int c = 0; c < 4; c++) acc[a][b][c] = 0.f;

    load_stage(sb, 0, Ah, Al, Bh, Bl, bm, bn, 0, tid); CP_COMMIT();
    load_stage(sb, 1, Ah, Al, Bh, Bl, bm, bn, 1, tid); CP_COMMIT();

    for (int kc = 0; kc < KT; kc++) {
        CP_WAIT(1);
        __syncthreads();
        if (kc + 2 < KT)
            load_stage(sb, (kc + 2) % NSTG, Ah, Al, Bh, Bl, bm, bn, kc + 2, tid);
        CP_COMMIT();

        uint32_t st = sb + (kc % NSTG) * STAGE_B;
#pragma unroll
        for (int ks = 0; ks < 2; ks++) {
            uint32_t ahf[4][4], alf[4][4], bhf[4][2], blf[4][2];
#pragma unroll
            for (int mt = 0; mt < 4; mt++) {
                int r = wm * 64 + mt * 16 + (lane & 15);
                int u = 2 * ks + (lane >> 4);
                uint32_t a_addr = st + swz(r, u);
                ldsm4(ahf[mt], a_addr);
                ldsm4(alf[mt], a_addr + PLANE_B);
            }
#pragma unroll
            for (int np = 0; np < 2; np++) {
                int r = wn * 32 + np * 16 + (lane & 7) + ((lane >> 4) & 1) * 8;
                int u = 2 * ks + ((lane >> 3) & 1);
                uint32_t b_addr = st + 2 * PLANE_B + swz(r, u);
                uint32_t t[4];
                ldsm4(t, b_addr);
                bhf[np*2][0] = t[0]; bhf[np*2][1] = t[1];
                bhf[np*2+1][0] = t[2]; bhf[np*2+1][1] = t[3];
                ldsm4(t, b_addr + PLANE_B);
                blf[np*2][0] = t[0]; blf[np*2][1] = t[1];
                blf[np*2+1][0] = t[2]; blf[np*2+1][1] = t[3];
            }
#pragma unroll
            for (int mt = 0; mt < 4; mt++)
#pragma unroll
                for (int nt = 0; nt < 4; nt++) {
                    mma16816(acc[mt][nt], ahf[mt], bhf[nt]);
                    mma16816(acc[mt][nt], ahf[mt], blf[nt]);
                    mma16816(acc[mt][nt], alf[mt], bhf[nt]);
                }
        }
    }

#pragma unroll
    for (int mt = 0; mt < 4; mt++)
#pragma unroll
        for (int nt = 0; nt < 4; nt++) {
            float* c = acc[mt][nt];
            int row = bm * 128 + wm * 64 + mt * 16 + (lane >> 2);
            int col = bn * 128 + wn * 32 + nt * 8 + 2 * (lane & 3);
            *(float2*)(out + (size_t)row * ldc + col) = make_float2(c[0], c[1]);
            *(float2*)(out + (size_t)(row + 8) * ldc + col) = make_float2(c[2], c[3]);
        }
}

// ---------------------------------------------------------------------------
// QKNorm + partial 2D RoPE. One warp per (row, head-vector).
// ---------------------------------------------------------------------------
__global__ __launch_bounds__(256)
void norm_rope2(const float* __restrict__ qw, const float* __restrict__ kw) {
    int vec = blockIdx.x * 8 + (threadIdx.x >> 5);
    int lane = threadIdx.x & 31;
    int hh = vec % (NH + NKV);
    int row = vec / (NH + NKV);
    bool is_q = hh < NH;
    int col = is_q ? hh * HD : GDIM + (hh - NH) * HD;
    float* p = g_qkv + (size_t)row * QKV_N + col;
    float v0 = p[lane], v1 = p[lane + 32];
    float sq = v0 * v0 + v1 * v1;
#pragma unroll
    for (int o = 16; o; o >>= 1) sq += __shfl_xor_sync(0xffffffffu, sq, o);
    float scl = rsqrtf(sq * (1.0f / HD) + 1e-6f);
    const float* wv = is_q ? qw : kw;
    v0 *= scl * wv[lane];
    v1 *= scl * wv[lane + 32];
    int s = row % SEQ;
    if (s < NZ) {
        int j = lane & 15;
        float pos = (lane < 16) ? (float)(s >> 4) : (float)(s & 15);
        float invf = __expf(-(float)j * 0.57564627324851142f);
        float c, sn;
        sincosf(pos * invf, &sn, &c);
        float o0 = v0 * c - v1 * sn;
        float o1 = v1 * c + v0 * sn;
        v0 = o0; v1 = o1;
    }
    p[lane] = v0;
    p[lane + 32] = v1;
}

// ---------------------------------------------------------------------------
// Attention (fp32, smem-resident KV). Epilogue writes row-major split planes.
// ---------------------------------------------------------------------------
__global__ void __launch_bounds__(288, 1) attn_kernel() {
    int h  = blockIdx.x;
    int bt = blockIdx.y;
    extern __shared__ __align__(16) float sm[];
    float* Ks = sm;
    float* Vs = sm + SEQ * HD;
    int tid = threadIdx.x;
    int kvh = h >> 2;
    const float* base = g_qkv + (size_t)bt * SEQ * QKV_N;
    int kcol = GDIM + kvh * HD;
    int vcol = GDIM + NKV * HD + kvh * HD;

    for (int f = tid; f < SEQ * HD / 4; f += blockDim.x) {
        int j = f >> 4;
        int d4 = (f & 15) << 2;
        *(float4*)(Ks + j * HD + d4) = *(const float4*)(base + (size_t)j * QKV_N + kcol + d4);
        *(float4*)(Vs + j * HD + d4) = *(const float4*)(base + (size_t)j * QKV_N + vcol + d4);
    }
    __syncthreads();

    if (tid >= SEQ) return;
    size_t row = (size_t)bt * SEQ + tid;
    const float* qp = g_qkv + row * QKV_N + h * HD;
    float4 q[16];
#pragma unroll
    for (int i = 0; i < 16; i++) q[i] = *(const float4*)(qp + i * 4);

    float4 acc[16];
#pragma unroll
    for (int i = 0; i < 16; i++) acc[i] = make_float4(0.f, 0.f, 0.f, 0.f);
    float l = 0.f;

    for (int j = 0; j < SEQ; j++) {
        const float4* kr = (const float4*)(Ks + j * HD);
        float s0 = 0.f, s1 = 0.f, s2 = 0.f, s3 = 0.f;
#pragma unroll
        for (int i = 0; i < 16; i++) {
            float4 kv = kr[i];
            s0 += q[i].x * kv.x; s1 += q[i].y * kv.y;
            s2 += q[i].z * kv.z; s3 += q[i].w * kv.w;
        }
        float s = ((s0 + s1) + (s2 + s3)) * 0.125f;
        s = 50.0f * tanhf(s * 0.02f);
        float p = __expf(s);
        l += p;
        const float4* vr = (const float4*)(Vs + j * HD);
#pragma unroll
        for (int i = 0; i < 16; i++) {
            float4 vv = vr[i];
            acc[i].x += p * vv.x; acc[i].y += p * vv.y;
            acc[i].z += p * vv.z; acc[i].w += p * vv.w;
        }
    }

    float inv = 1.0f / l;
    __nv_bfloat16* hp = g_ahi + row * GDIM + h * HD;
    __nv_bfloat16* lp = g_alo + row * GDIM + h * HD;
#pragma unroll
    for (int j = 0; j < 8; j++) {
        float f[8] = {acc[2*j].x * inv, acc[2*j].y * inv, acc[2*j].z * inv, acc[2*j].w * inv,
                      acc[2*j+1].x * inv, acc[2*j+1].y * inv, acc[2*j+1].z * inv, acc[2*j+1].w * inv};
        uint16_t hb[8], lb[8];
#pragma unroll
        for (int e = 0; e < 8; e++) {
            __nv_bfloat16 hv = __float2bfloat16(f[e]);
            float rr = f[e] - __bfloat162float(hv);
            hb[e] = __bfloat16_as_ushort(hv);
            lb[e] = __bfloat16_as_ushort(__float2bfloat16(rr));
        }
        uint4 hv4, lv4;
        hv4.x = hb[0] | ((uint32_t)hb[1] << 16); hv4.y = hb[2] | ((uint32_t)hb[3] << 16);
        hv4.z = hb[4] | ((uint32_t)hb[5] << 16); hv4.w = hb[6] | ((uint32_t)hb[7] << 16);
        lv4.x = lb[0] | ((uint32_t)lb[1] << 16); lv4.y = lb[2] | ((uint32_t)lb[3] << 16);
        lv4.z = lb[4] | ((uint32_t)lb[5] << 16); lv4.w = lb[6] | ((uint32_t)lb[7] << 16);
        *(uint4*)(hp + j * 8) = hv4;
        *(uint4*)(lp + j * 8) = lv4;
    }
}

// ---------------------------------------------------------------------------
extern "C" void kernel_launch(void* const* d_in, const int* in_sizes, int n_in,
                              void* d_out, int out_size) {
    const float* x   = (const float*)d_in[0];
    const float* wq  = (const float*)d_in[1];
    const float* wk  = (const float*)d_in[2];
    const float* wv  = (const float*)d_in[3];
    const float* wo  = (const float*)d_in[4];
    const float* qnw = (const float*)d_in[5];
    const float* knw = (const float*)d_in[6];
    float* out = (float*)d_out;

    __nv_bfloat16 *xhi, *xlo, *whi, *wlo, *wohi, *wolo, *ahi, *alo;
    float* qkv;
    cudaGetSymbolAddress((void**)&xhi, g_xhi);
    cudaGetSymbolAddress((void**)&xlo, g_xlo);
    cudaGetSymbolAddress((void**)&whi, g_whi);
    cudaGetSymbolAddress((void**)&wlo, g_wlo);
    cudaGetSymbolAddress((void**)&wohi, g_wohi);
    cudaGetSymbolAddress((void**)&wolo, g_wolo);
    cudaGetSymbolAddress((void**)&ahi, g_ahi);
    cudaGetSymbolAddress((void**)&alo, g_alo);
    cudaGetSymbolAddress((void**)&qkv, g_qkv);

    cudaFuncSetAttribute((const void*)gemm_mma,
                         cudaFuncAttributeMaxDynamicSharedMemorySize, GEMM_SMEM);
    const int attn_smem = 2 * SEQ * HD * (int)sizeof(float);
    cudaFuncSetAttribute((const void*)attn_kernel,
                         cudaFuncAttributeMaxDynamicSharedMemorySize, attn_smem);

    // 1) split operands into row-major bf16 hi/lo planes
    split_rm<<<4224, 256>>>(x, xhi, xlo, MROWS * GDIM / 8);
    split_w_qkv<<<768, 256>>>(wq, wk, wv);
    split_rm<<<512, 256>>>(wo, wohi, wolo, GDIM * GDIM / 8);

    // 2) QKV projection
    gemm_mma<<<dim3(QKV_N / 128, MROWS / 128), 256, GEMM_SMEM>>>(
        xhi, xlo, whi, wlo, qkv, QKV_N);

    // 3) QKNorm + 2D RoPE
    norm_rope2<<<(MROWS * (NH + NKV)) / 8, 256>>>(qnw, knw);

    // 4) attention (writes row-major split planes for the O gemm)
    attn_kernel<<<dim3(NH, BTN), 288, attn_smem>>>();

    // 5) output projection straight into d_out
    gemm_mma<<<dim3(GDIM / 128, MROWS / 128), 256, GEMM_SMEM>>>(
        ahi, alo, wohi, wolo, out, GDIM);
}

// round 4
// speedup vs baseline: 2.2433x; 1.2248x over previous
#include <cuda_runtime.h>
#include <cuda_bf16.h>
#include <stdint.h>
#include <math.h>

// Problem constants
#define BTN   64
#define SEQ   264
#define MROWS (BTN*SEQ)      // 16896
#define GDIM  1024
#define NH    16
#define NKV   4
#define HD    64
#define QKV_N 1536
#define NZ    256

// GEMM tiling
#define BK    32
#define KT    (GDIM/BK)      // 32 k-chunks
#define NSTG  3
#define STAGE_B 32768
#define PLANE_B 8192
#define GEMM_SMEM (NSTG*STAGE_B)   // 98304

// Attention smem layout (bf16 planes, rows padded to 72 elems = 144 B)
#define KPAD  272
#define LDP   144
#define KPL   (KPAD*LDP)     // 39168
#define QPL   (96*LDP)       // 13824
#define SM_KHI 0
#define SM_KLO (KPL)
#define SM_VHI (2*KPL)
#define SM_VLO (3*KPL)
#define SM_QHI (4*KPL)
#define SM_QLO (4*KPL + QPL)
#define ATT_SMEM (4*KPL + 2*QPL)   // 184320

// ---------------------------------------------------------------------------
// device scratch
// ---------------------------------------------------------------------------
__device__ __align__(16) __nv_bfloat16 g_xhi[(size_t)MROWS * GDIM];
__device__ __align__(16) __nv_bfloat16 g_xlo[(size_t)MROWS * GDIM];
__device__ __align__(16) __nv_bfloat16 g_whi[(size_t)QKV_N * GDIM];
__device__ __align__(16) __nv_bfloat16 g_wlo[(size_t)QKV_N * GDIM];
__device__ __align__(16) __nv_bfloat16 g_wohi[(size_t)GDIM * GDIM];
__device__ __align__(16) __nv_bfloat16 g_wolo[(size_t)GDIM * GDIM];
__device__ __align__(16) __nv_bfloat16 g_ahi[(size_t)MROWS * GDIM];
__device__ __align__(16) __nv_bfloat16 g_alo[(size_t)MROWS * GDIM];
__device__ __align__(16) float         g_qkv[(size_t)MROWS * QKV_N];

// ---------------------------------------------------------------------------
// helpers
// ---------------------------------------------------------------------------
__device__ __forceinline__ uint32_t smem_u32(const void* p) {
    uint32_t a;
    asm("{ .reg .u64 t; cvta.to.shared.u64 t, %1; cvt.u32.u64 %0, t; }"
        : "=r"(a) : "l"(p));
    return a;
}
__device__ __forceinline__ void cp16(uint32_t dst, const void* src) {
    asm volatile("cp.async.cg.shared.global [%0], [%1], 16;" :: "r"(dst), "l"(src));
}
#define CP_COMMIT() asm volatile("cp.async.commit_group;" ::: "memory")
#define CP_WAIT(n)  asm volatile("cp.async.wait_group %0;" :: "n"(n) : "memory")

__device__ __forceinline__ void ldsm4(uint32_t* r, uint32_t addr) {
    asm volatile("ldmatrix.sync.aligned.m8n8.x4.shared.b16 {%0,%1,%2,%3}, [%4];"
                 : "=r"(r[0]), "=r"(r[1]), "=r"(r[2]), "=r"(r[3]) : "r"(addr));
}
__device__ __forceinline__ void ldsm4t(uint32_t* r, uint32_t addr) {
    asm volatile("ldmatrix.sync.aligned.m8n8.x4.trans.shared.b16 {%0,%1,%2,%3}, [%4];"
                 : "=r"(r[0]), "=r"(r[1]), "=r"(r[2]), "=r"(r[3]) : "r"(addr));
}
__device__ __forceinline__ void mma16816(float* c, const uint32_t* a, const uint32_t* b) {
    asm volatile(
        "mma.sync.aligned.m16n8k16.row.col.f32.bf16.bf16.f32 "
        "{%0,%1,%2,%3}, {%4,%5,%6,%7}, {%8,%9}, {%0,%1,%2,%3};"
        : "+f"(c[0]), "+f"(c[1]), "+f"(c[2]), "+f"(c[3])
        : "r"(a[0]), "r"(a[1]), "r"(a[2]), "r"(a[3]), "r"(b[0]), "r"(b[1]));
}

__device__ __forceinline__ uint32_t swz(int r, int u) {
    return (uint32_t)(r * 64 + ((u ^ ((r >> 1) & 3)) << 4));
}

// split two floats -> hi bf16x2 + lo bf16x2
__device__ __forceinline__ void split2(float a, float b, uint32_t& h, uint32_t& l) {
    __nv_bfloat16 ha = __float2bfloat16(a);
    __nv_bfloat16 hb = __float2bfloat16(b);
    float ra = a - __bfloat162float(ha);
    float rb = b - __bfloat162float(hb);
    h = (uint32_t)__bfloat16_as_ushort(ha) | ((uint32_t)__bfloat16_as_ushort(hb) << 16);
    l = (uint32_t)__bfloat16_as_ushort(__float2bfloat16(ra)) |
        ((uint32_t)__bfloat16_as_ushort(__float2bfloat16(rb)) << 16);
}

__device__ __forceinline__ void split8(const float* __restrict__ s, uint4& hv, uint4& lv) {
    float4 f0 = *(const float4*)s;
    float4 f1 = *(const float4*)(s + 4);
    split2(f0.x, f0.y, hv.x, lv.x);
    split2(f0.z, f0.w, hv.y, lv.y);
    split2(f1.x, f1.y, hv.z, lv.z);
    split2(f1.z, f1.w, hv.w, lv.w);
}

// ---------------------------------------------------------------------------
// split kernels
// ---------------------------------------------------------------------------
__global__ void split_rm(const float* __restrict__ src, __nv_bfloat16* __restrict__ hi,
                         __nv_bfloat16* __restrict__ lo, int nunits) {
    for (int i = blockIdx.x * blockDim.x + threadIdx.x; i < nunits;
         i += gridDim.x * blockDim.x) {
        uint4 hv, lv;
        split8(src + (size_t)i * 8, hv, lv);
        ((uint4*)hi)[i] = hv;
        ((uint4*)lo)[i] = lv;
    }
}

__global__ void split_w_qkv(const float* __restrict__ wq, const float* __restrict__ wk,
                            const float* __restrict__ wv) {
    int nunits = QKV_N * (GDIM / 8);
    for (int i = blockIdx.x * blockDim.x + threadIdx.x; i < nunits;
         i += gridDim.x * blockDim.x) {
        int row = i >> 7, ur = i & 127;
        const float* srow;
        if (row < NH * HD)                srow = wq + (size_t)row * GDIM;
        else if (row < NH*HD + NKV*HD)    srow = wk + (size_t)(row - NH*HD) * GDIM;
        else                              srow = wv + (size_t)(row - NH*HD - NKV*HD) * GDIM;
        uint4 hv, lv;
        split8(srow + ur * 8, hv, lv);
        ((uint4*)g_whi)[i] = hv;
        ((uint4*)g_wlo)[i] = lv;
    }
}

// ---------------------------------------------------------------------------
// bf16x3 GEMM via mma.sync (unchanged from round 3)
// ---------------------------------------------------------------------------
__device__ __forceinline__ void load_stage(uint32_t sb, int stage,
        const __nv_bfloat16* __restrict__ Ah, const __nv_bfloat16* __restrict__ Al,
        const __nv_bfloat16* __restrict__ Bh, const __nv_bfloat16* __restrict__ Bl,
        int bm, int bn, int kc, int tid) {
    uint32_t st = sb + stage * STAGE_B;
#pragma unroll
    for (int i = 0; i < 8; i++) {
        int v = i * 256 + tid;
        int op = v >> 9;
        int w = v & 511;
        int r = w >> 2, u = w & 3;
        const __nv_bfloat16* base = (op == 0) ? Ah : (op == 1) ? Al : (op == 2) ? Bh : Bl;
        int grow = ((op < 2) ? bm : bn) * 128 + r;
        const __nv_bfloat16* g = base + (size_t)grow * GDIM + kc * BK + u * 8;
        cp16(st + op * PLANE_B + swz(r, u), g);
    }
}

__global__ __launch_bounds__(256, 1)
void gemm_mma(const __nv_bfloat16* __restrict__ Ah, const __nv_bfloat16* __restrict__ Al,
              const __nv_bfloat16* __restrict__ Bh, const __nv_bfloat16* __restrict__ Bl,
              float* __restrict__ out, int ldc) {
    extern __shared__ __align__(1024) char smem[];
    uint32_t sb = smem_u32(smem);
    int tid = threadIdx.x, wid = tid >> 5, lane = tid & 31;
    int bm = blockIdx.y, bn = blockIdx.x;
    int wm = wid >> 2;
    int wn = wid & 3;

    float acc[4][4][4];
#pragma unroll
    for (int a = 0; a < 4; a++)
#pragma unroll
        for (int b = 0; b < 4; b++)
#pragma unroll
            for (int c = 0; c < 4; c++) acc[a][b][c] = 0.f;

    load_stage(sb, 0, Ah, Al, Bh, Bl, bm, bn, 0, tid); CP_COMMIT();
    load_stage(sb, 1, Ah, Al, Bh, Bl, bm, bn, 1, tid); CP_COMMIT();

    for (int kc = 0; kc < KT; kc++) {
        CP_WAIT(1);
        __syncthreads();
        if (kc + 2 < KT)
            load_stage(sb, (kc + 2) % NSTG, Ah, Al, Bh, Bl, bm, bn, kc + 2, tid);
        CP_COMMIT();

        uint32_t st = sb + (kc % NSTG) * STAGE_B;
#pragma unroll
        for (int ks = 0; ks < 2; ks++) {
            uint32_t ahf[4][4], alf[4][4], bhf[4][2], blf[4][2];
#pragma unroll
            for (int mt = 0; mt < 4; mt++) {
                int r = wm * 64 + mt * 16 + (lane & 15);
                int u = 2 * ks + (lane >> 4);
                uint32_t a_addr = st + swz(r, u);
                ldsm4(ahf[mt], a_addr);
                ldsm4(alf[mt], a_addr + PLANE_B);
            }
#pragma unroll
            for (int np = 0; np < 2; np++) {
                int r = wn * 32 + np * 16 + (lane & 7) + ((lane >> 4) & 1) * 8;
                int u = 2 * ks + ((lane >> 3) & 1);
                uint32_t b_addr = st + 2 * PLANE_B + swz(r, u);
                uint32_t t[4];
                ldsm4(t, b_addr);
                bhf[np*2][0] = t[0]; bhf[np*2][1] = t[1];
                bhf[np*2+1][0] = t[2]; bhf[np*2+1][1] = t[3];
                ldsm4(t, b_addr + PLANE_B);
                blf[np*2][0] = t[0]; blf[np*2][1] = t[1];
                blf[np*2+1][0] = t[2]; blf[np*2+1][1] = t[3];
            }
#pragma unroll
            for (int mt = 0; mt < 4; mt++)
#pragma unroll
                for (int nt = 0; nt < 4; nt++) {
                    mma16816(acc[mt][nt], ahf[mt], bhf[nt]);
                    mma16816(acc[mt][nt], ahf[mt], blf[nt]);
                    mma16816(acc[mt][nt], alf[mt], bhf[nt]);
                }
        }
    }

#pragma unroll
    for (int mt = 0; mt < 4; mt++)
#pragma unroll
        for (int nt = 0; nt < 4; nt++) {
            float* c = acc[mt][nt];
            int row = bm * 128 + wm * 64 + mt * 16 + (lane >> 2);
            int col = bn * 128 + wn * 32 + nt * 8 + 2 * (lane & 3);
            *(float2*)(out + (size_t)row * ldc + col) = make_float2(c[0], c[1]);
            *(float2*)(out + (size_t)(row + 8) * ldc + col) = make_float2(c[2], c[3]);
        }
}

// ---------------------------------------------------------------------------
// QKNorm + partial 2D RoPE (unchanged)
// ---------------------------------------------------------------------------
__global__ __launch_bounds__(256)
void norm_rope2(const float* __restrict__ qw, const float* __restrict__ kw) {
    int vec = blockIdx.x * 8 + (threadIdx.x >> 5);
    int lane = threadIdx.x & 31;
    int hh = vec % (NH + NKV);
    int row = vec / (NH + NKV);
    bool is_q = hh < NH;
    int col = is_q ? hh * HD : GDIM + (hh - NH) * HD;
    float* p = g_qkv + (size_t)row * QKV_N + col;
    float v0 = p[lane], v1 = p[lane + 32];
    float sq = v0 * v0 + v1 * v1;
#pragma unroll
    for (int o = 16; o; o >>= 1) sq += __shfl_xor_sync(0xffffffffu, sq, o);
    float scl = rsqrtf(sq * (1.0f / HD) + 1e-6f);
    const float* wv = is_q ? qw : kw;
    v0 *= scl * wv[lane];
    v1 *= scl * wv[lane + 32];
    int s = row % SEQ;
    if (s < NZ) {
        int j = lane & 15;
        float pos = (lane < 16) ? (float)(s >> 4) : (float)(s & 15);
        float invf = __expf(-(float)j * 0.57564627324851142f);
        float c, sn;
        sincosf(pos * invf, &sn, &c);
        float o0 = v0 * c - v1 * sn;
        float o1 = v1 * c + v0 * sn;
        v0 = o0; v1 = o1;
    }
    p[lane] = v0;
    p[lane + 32] = v1;
}

// ---------------------------------------------------------------------------
// Flash-style mma attention.
// grid (3 m-tiles, NH, BTN); 6 warps; m-tile starts {0, 96, 168} (24-row
// overlap -> deterministic duplicate writes). K/V/Q in smem bf16 hi/lo planes,
// rows padded to 72 elems (LDSM conflict-free). Softcap -> no running max.
// ---------------------------------------------------------------------------
__device__ __forceinline__ void st_split4(char* hi, char* lo, float4 f) {
    uint32_t h0, l0, h1, l1;
    split2(f.x, f.y, h0, l0);
    split2(f.z, f.w, h1, l1);
    ((uint32_t*)hi)[0] = h0; ((uint32_t*)hi)[1] = h1;
    ((uint32_t*)lo)[0] = l0; ((uint32_t*)lo)[1] = l1;
}

__global__ __launch_bounds__(192, 1) void attn_mma() {
    extern __shared__ __align__(1024) char smem[];
    const int tid = threadIdx.x;
    const int mt = blockIdx.x, h = blockIdx.y, bt = blockIdx.z;
    const int m0 = (mt == 0) ? 0 : (mt == 1 ? 96 : 168);
    const int kvh = h >> 2;
    const float* gq = g_qkv + (size_t)bt * SEQ * QKV_N;
    const int kcol = GDIM + kvh * HD;
    const int vcol = GDIM + NKV * HD + kvh * HD;

    // ---- load K/V (264 rows) + Q (96 rows) into split bf16 smem planes ----
    for (int idx = tid; idx < SEQ * 16; idx += 192) {
        int r = idx >> 4, u = idx & 15;
        const float* rp = gq + (size_t)r * QKV_N;
        float4 kk = *(const float4*)(rp + kcol + u * 4);
        float4 vv = *(const float4*)(rp + vcol + u * 4);
        int off = r * LDP + u * 8;
        st_split4(smem + SM_KHI + off, smem + SM_KLO + off, kk);
        st_split4(smem + SM_VHI + off, smem + SM_VLO + off, vv);
    }
    for (int idx = tid; idx < 96 * 16; idx += 192) {
        int r = idx >> 4, u = idx & 15;
        float4 qq = *(const float4*)(gq + (size_t)(m0 + r) * QKV_N + h * HD + u * 4);
        int off = r * LDP + u * 8;
        st_split4(smem + SM_QHI + off, smem + SM_QLO + off, qq);
    }
    // zero pad rows 264..271 of K/V planes
    for (int idx = tid; idx < 8 * 36; idx += 192) {
        int off = (SEQ + idx / 36) * LDP + (idx % 36) * 4;
        *(uint32_t*)(smem + SM_KHI + off) = 0;
        *(uint32_t*)(smem + SM_KLO + off) = 0;
        *(uint32_t*)(smem + SM_VHI + off) = 0;
        *(uint32_t*)(smem + SM_VLO + off) = 0;
    }
    __syncthreads();

    const uint32_t sb = smem_u32(smem);
    const int w = tid >> 5, lane = tid & 31;

    // ---- preload Q A-fragments (hi/lo), 4 k16 chunks ----
    uint32_t qh[4][4], ql[4][4];
    {
        int r = w * 16 + (lane & 15);
        int uo = lane >> 4;
#pragma unroll
        for (int kc = 0; kc < 4; kc++) {
            uint32_t off = (uint32_t)(r * LDP + (2 * kc + uo) * 16);
            ldsm4(qh[kc], sb + SM_QHI + off);
            ldsm4(ql[kc], sb + SM_QLO + off);
        }
    }

    float oacc[8][4];
#pragma unroll
    for (int i = 0; i < 8; i++)
#pragma unroll
        for (int j = 0; j < 4; j++) oacc[i][j] = 0.f;
    float lsum0 = 0.f, lsum1 = 0.f;

    const int krow = (lane & 7) + ((lane >> 4) & 1) * 8;
    const int ku = (lane >> 3) & 1;
    const int vrow = (lane & 7) + ((lane >> 3) & 1) * 8;
    const int vu = (lane >> 4) & 1;

    for (int np = 0; np < 17; np++) {
        // ---- S = Q K^T for 16 keys (2 n8 blocks), 3 bf16 planes ----
        float sc[2][4] = {{0.f,0.f,0.f,0.f},{0.f,0.f,0.f,0.f}};
#pragma unroll
        for (int kc = 0; kc < 4; kc++) {
            uint32_t off = (uint32_t)((np * 16 + krow) * LDP + (2 * kc + ku) * 16);
            uint32_t bh[4], bl[4];
            ldsm4(bh, sb + SM_KHI + off);
            ldsm4(bl, sb + SM_KLO + off);
            mma16816(sc[0], qh[kc], bh);
            mma16816(sc[0], qh[kc], bl);
            mma16816(sc[0], ql[kc], bh);
            mma16816(sc[1], qh[kc], bh + 2);
            mma16816(sc[1], qh[kc], bl + 2);
            mma16816(sc[1], ql[kc], bh + 2);
        }
        // ---- softcap + exp ----
        float pf[2][4];
#pragma unroll
        for (int nb = 0; nb < 2; nb++)
#pragma unroll
            for (int e = 0; e < 4; e++) {
                float s = sc[nb][e] * 0.125f;               // * HD^-0.5
                float t = __expf(-0.04f * fabsf(s));        // e^{-2|s|/50}
                float th = __fdividef(1.f - t, 1.f + t);    // tanh(|s|/50)
                float cap = (s >= 0.f) ? 50.f * th : -50.f * th;
                pf[nb][e] = __expf(cap);
            }
        if (np == 16) { pf[1][0] = pf[1][1] = pf[1][2] = pf[1][3] = 0.f; }
        lsum0 += pf[0][0] + pf[0][1] + pf[1][0] + pf[1][1];
        lsum1 += pf[0][2] + pf[0][3] + pf[1][2] + pf[1][3];

        // ---- P -> A-fragment (hi/lo) ----
        uint32_t ph[4], pl[4];
        split2(pf[0][0], pf[0][1], ph[0], pl[0]);
        split2(pf[0][2], pf[0][3], ph[1], pl[1]);
        split2(pf[1][0], pf[1][1], ph[2], pl[2]);
        split2(pf[1][2], pf[1][3], ph[3], pl[3]);

        // ---- O += P V, V via ldmatrix.trans, 3 planes ----
#pragma unroll
        for (int db = 0; db < 4; db++) {
            uint32_t off = (uint32_t)((np * 16 + vrow) * LDP + (2 * db + vu) * 16);
            uint32_t vh[4], vl[4];
            ldsm4t(vh, sb + SM_VHI + off);
            ldsm4t(vl, sb + SM_VLO + off);
            mma16816(oacc[2*db],     ph, vh);
            mma16816(oacc[2*db],     ph, vl);
            mma16816(oacc[2*db],     pl, vh);
            mma16816(oacc[2*db+1],   ph, vh + 2);
            mma16816(oacc[2*db+1],   ph, vl + 2);
            mma16816(oacc[2*db+1],   pl, vh + 2);
        }
    }

    // ---- normalize + write split bf16 output ----
    lsum0 += __shfl_xor_sync(0xffffffffu, lsum0, 1);
    lsum0 += __shfl_xor_sync(0xffffffffu, lsum0, 2);
    lsum1 += __shfl_xor_sync(0xffffffffu, lsum1, 1);
    lsum1 += __shfl_xor_sync(0xffffffffu, lsum1, 2);
    float inv0 = __fdividef(1.f, lsum0);
    float inv1 = __fdividef(1.f, lsum1);

    size_t row0 = (size_t)bt * SEQ + m0 + w * 16 + (lane >> 2);
    int colb = h * HD + 2 * (lane & 3);
#pragma unroll
    for (int nb = 0; nb < 8; nb++) {
        int col = colb + nb * 8;
        uint32_t hv, lv;
        split2(oacc[nb][0] * inv0, oacc[nb][1] * inv0, hv, lv);
        *(uint32_t*)(g_ahi + row0 * GDIM + col) = hv;
        *(uint32_t*)(g_alo + row0 * GDIM + col) = lv;
        split2(oacc[nb][2] * inv1, oacc[nb][3] * inv1, hv, lv);
        *(uint32_t*)(g_ahi + (row0 + 8) * GDIM + col) = hv;
        *(uint32_t*)(g_alo + (row0 + 8) * GDIM + col) = lv;
    }
}

// ---------------------------------------------------------------------------
extern "C" void kernel_launch(void* const* d_in, const int* in_sizes, int n_in,
                              void* d_out, int out_size) {
    const float* x   = (const float*)d_in[0];
    const float* wq  = (const float*)d_in[1];
    const float* wk  = (const float*)d_in[2];
    const float* wv  = (const float*)d_in[3];
    const float* wo  = (const float*)d_in[4];
    const float* qnw = (const float*)d_in[5];
    const float* knw = (const float*)d_in[6];
    float* out = (float*)d_out;

    __nv_bfloat16 *xhi, *xlo, *whi, *wlo, *wohi, *wolo, *ahi, *alo;
    float* qkv;
    cudaGetSymbolAddress((void**)&xhi, g_xhi);
    cudaGetSymbolAddress((void**)&xlo, g_xlo);
    cudaGetSymbolAddress((void**)&whi, g_whi);
    cudaGetSymbolAddress((void**)&wlo, g_wlo);
    cudaGetSymbolAddress((void**)&wohi, g_wohi);
    cudaGetSymbolAddress((void**)&wolo, g_wolo);
    cudaGetSymbolAddress((void**)&ahi, g_ahi);
    cudaGetSymbolAddress((void**)&alo, g_alo);
    cudaGetSymbolAddress((void**)&qkv, g_qkv);

    cudaFuncSetAttribute((const void*)gemm_mma,
                         cudaFuncAttributeMaxDynamicSharedMemorySize, GEMM_SMEM);
    cudaFuncSetAttribute((const void*)attn_mma,
                         cudaFuncAttributeMaxDynamicSharedMemorySize, ATT_SMEM);

    // 1) split operands into bf16 hi/lo planes
    split_rm<<<4224, 256>>>(x, xhi, xlo, MROWS * GDIM / 8);
    split_w_qkv<<<768, 256>>>(wq, wk, wv);
    split_rm<<<512, 256>>>(wo, wohi, wolo, GDIM * GDIM / 8);

    // 2) QKV projection
    gemm_mma<<<dim3(QKV_N / 128, MROWS / 128), 256, GEMM_SMEM>>>(
        xhi, xlo, whi, wlo, qkv, QKV_N);

    // 3) QKNorm + 2D RoPE
    norm_rope2<<<(MROWS * (NH + NKV)) / 8, 256>>>(qnw, knw);

    // 4) tensor-core attention (writes split planes for the O gemm)
    attn_mma<<<dim3(3, NH, BTN), 192, ATT_SMEM>>>();

    // 5) output projection
    gemm_mma<<<dim3(GDIM / 128, MROWS / 128), 256, GEMM_SMEM>>>(
        ahi, alo, wohi, wolo, out, GDIM);
}

// round 5
// speedup vs baseline: 2.2652x; 1.0097x over previous
#include <cuda_runtime.h>
#include <cuda_bf16.h>
#include <stdint.h>
#include <math.h>

// Problem constants
#define BTN   64
#define SEQ   264
#define MROWS (BTN*SEQ)      // 16896
#define GDIM  1024
#define NH    16
#define NKV   4
#define HD    64
#define QKV_N 1536
#define NZ    256

// GEMM tiling: block 128x256, BK=32, 8 warps (warptile 64x64), 3-stage
#define BK    32
#define KT    (GDIM/BK)      // 32
#define A_PL  8192           // 128x32 bf16
#define B_PL  16384          // 256x32 bf16
#define STG_B (2*A_PL + 2*B_PL)    // 49152
#define GEMM_SMEM (3*STG_B)        // 147456

// Attention smem layout (bf16 planes, rows padded to 72 elems = 144 B)
#define KPAD  272
#define LDP   144
#define KPL   (KPAD*LDP)
#define QPL   (96*LDP)
#define SM_KHI 0
#define SM_KLO (KPL)
#define SM_VHI (2*KPL)
#define SM_VLO (3*KPL)
#define SM_QHI (4*KPL)
#define SM_QLO (4*KPL + QPL)
#define ATT_SMEM (4*KPL + 2*QPL)   // 184320

// ---------------------------------------------------------------------------
// device scratch
// ---------------------------------------------------------------------------
__device__ __align__(16) __nv_bfloat16 g_xhi[(size_t)MROWS * GDIM];
__device__ __align__(16) __nv_bfloat16 g_xlo[(size_t)MROWS * GDIM];
__device__ __align__(16) __nv_bfloat16 g_whi[(size_t)QKV_N * GDIM];
__device__ __align__(16) __nv_bfloat16 g_wlo[(size_t)QKV_N * GDIM];
__device__ __align__(16) __nv_bfloat16 g_wohi[(size_t)GDIM * GDIM];
__device__ __align__(16) __nv_bfloat16 g_wolo[(size_t)GDIM * GDIM];
__device__ __align__(16) __nv_bfloat16 g_ahi[(size_t)MROWS * GDIM];
__device__ __align__(16) __nv_bfloat16 g_alo[(size_t)MROWS * GDIM];
__device__ __align__(16) float         g_qkv[(size_t)MROWS * QKV_N];

// ---------------------------------------------------------------------------
// helpers
// ---------------------------------------------------------------------------
__device__ __forceinline__ uint32_t smem_u32(const void* p) {
    uint32_t a;
    asm("{ .reg .u64 t; cvta.to.shared.u64 t, %1; cvt.u32.u64 %0, t; }"
        : "=r"(a) : "l"(p));
    return a;
}
__device__ __forceinline__ void cp16(uint32_t dst, const void* src) {
    asm volatile("cp.async.cg.shared.global [%0], [%1], 16;" :: "r"(dst), "l"(src));
}
#define CP_COMMIT() asm volatile("cp.async.commit_group;" ::: "memory")
#define CP_WAIT(n)  asm volatile("cp.async.wait_group %0;" :: "n"(n) : "memory")

__device__ __forceinline__ void ldsm4(uint32_t* r, uint32_t addr) {
    asm volatile("ldmatrix.sync.aligned.m8n8.x4.shared.b16 {%0,%1,%2,%3}, [%4];"
                 : "=r"(r[0]), "=r"(r[1]), "=r"(r[2]), "=r"(r[3]) : "r"(addr));
}
__device__ __forceinline__ void ldsm4t(uint32_t* r, uint32_t addr) {
    asm volatile("ldmatrix.sync.aligned.m8n8.x4.trans.shared.b16 {%0,%1,%2,%3}, [%4];"
                 : "=r"(r[0]), "=r"(r[1]), "=r"(r[2]), "=r"(r[3]) : "r"(addr));
}
__device__ __forceinline__ void mma16816(float* c, const uint32_t* a, const uint32_t* b) {
    asm volatile(
        "mma.sync.aligned.m16n8k16.row.col.f32.bf16.bf16.f32 "
        "{%0,%1,%2,%3}, {%4,%5,%6,%7}, {%8,%9}, {%0,%1,%2,%3};"
        : "+f"(c[0]), "+f"(c[1]), "+f"(c[2]), "+f"(c[3])
        : "r"(a[0]), "r"(a[1]), "r"(a[2]), "r"(a[3]), "r"(b[0]), "r"(b[1]));
}

// swizzled byte offset of 16B unit (r, u) within an Nx32 bf16 plane (64B rows)
__device__ __forceinline__ uint32_t swz(int r, int u) {
    return (uint32_t)(r * 64 + ((u ^ ((r >> 1) & 3)) << 4));
}

// split two floats -> hi bf16x2 + lo bf16x2
__device__ __forceinline__ void split2(float a, float b, uint32_t& h, uint32_t& l) {
    __nv_bfloat16 ha = __float2bfloat16(a);
    __nv_bfloat16 hb = __float2bfloat16(b);
    float ra = a - __bfloat162float(ha);
    float rb = b - __bfloat162float(hb);
    h = (uint32_t)__bfloat16_as_ushort(ha) | ((uint32_t)__bfloat16_as_ushort(hb) << 16);
    l = (uint32_t)__bfloat16_as_ushort(__float2bfloat16(ra)) |
        ((uint32_t)__bfloat16_as_ushort(__float2bfloat16(rb)) << 16);
}

__device__ __forceinline__ void split8(const float* __restrict__ s, uint4& hv, uint4& lv) {
    float4 f0 = *(const float4*)s;
    float4 f1 = *(const float4*)(s + 4);
    split2(f0.x, f0.y, hv.x, lv.x);
    split2(f0.z, f0.w, hv.y, lv.y);
    split2(f1.x, f1.y, hv.z, lv.z);
    split2(f1.z, f1.w, hv.w, lv.w);
}

// ---------------------------------------------------------------------------
// split kernels
// ---------------------------------------------------------------------------
__global__ void split_rm(const float* __restrict__ src, __nv_bfloat16* __restrict__ hi,
                         __nv_bfloat16* __restrict__ lo, int nunits) {
    for (int i = blockIdx.x * blockDim.x + threadIdx.x; i < nunits;
         i += gridDim.x * blockDim.x) {
        uint4 hv, lv;
        split8(src + (size_t)i * 8, hv, lv);
        ((uint4*)hi)[i] = hv;
        ((uint4*)lo)[i] = lv;
    }
}

__global__ void split_w_qkv(const float* __restrict__ wq, const float* __restrict__ wk,
                            const float* __restrict__ wv) {
    int nunits = QKV_N * (GDIM / 8);
    for (int i = blockIdx.x * blockDim.x + threadIdx.x; i < nunits;
         i += gridDim.x * blockDim.x) {
        int row = i >> 7, ur = i & 127;
        const float* srow;
        if (row < NH * HD)                srow = wq + (size_t)row * GDIM;
        else if (row < NH*HD + NKV*HD)    srow = wk + (size_t)(row - NH*HD) * GDIM;
        else                              srow = wv + (size_t)(row - NH*HD - NKV*HD) * GDIM;
        uint4 hv, lv;
        split8(srow + ur * 8, hv, lv);
        ((uint4*)g_whi)[i] = hv;
        ((uint4*)g_wlo)[i] = lv;
    }
}

// ---------------------------------------------------------------------------
// bf16x3 GEMM via mma.sync: out[m][n] = sum_k A[m][k]*B[n][k], K=1024
// block 128x256, BK=32, 8 warps (warptile 64x64), 3-stage cp.async pipeline
// ---------------------------------------------------------------------------
__device__ __forceinline__ void load_stage(uint32_t sb, int stage,
        const __nv_bfloat16* __restrict__ Ah, const __nv_bfloat16* __restrict__ Al,
        const __nv_bfloat16* __restrict__ Bh, const __nv_bfloat16* __restrict__ Bl,
        int bm, int bn, int kc, int tid) {
    uint32_t st = sb + stage * STG_B;
    // A planes: 128 rows x 4 units x 2 planes = 1024 units
#pragma unroll
    for (int i = 0; i < 4; i++) {
        int v = i * 256 + tid;
        int op = v >> 9, w = v & 511;
        int r = w >> 2, u = w & 3;
        const __nv_bfloat16* base = op ? Al : Ah;
        const __nv_bfloat16* g = base + (size_t)(bm * 128 + r) * GDIM + kc * BK + u * 8;
        cp16(st + op * A_PL + swz(r, u), g);
    }
    // B planes: 256 rows x 4 units x 2 planes = 2048 units
#pragma unroll
    for (int i = 0; i < 8; i++) {
        int v = i * 256 + tid;
        int op = v >> 10, w = v & 1023;
        int r = w >> 2, u = w & 3;
        const __nv_bfloat16* base = op ? Bl : Bh;
        const __nv_bfloat16* g = base + (size_t)(bn * 256 + r) * GDIM + kc * BK + u * 8;
        cp16(st + 2 * A_PL + op * B_PL + swz(r, u), g);
    }
}

__global__ __launch_bounds__(256, 1)
void gemm_mma(const __nv_bfloat16* __restrict__ Ah, const __nv_bfloat16* __restrict__ Al,
              const __nv_bfloat16* __restrict__ Bh, const __nv_bfloat16* __restrict__ Bl,
              float* __restrict__ out, int ldc) {
    extern __shared__ __align__(1024) char smem[];
    uint32_t sb = smem_u32(smem);
    int tid = threadIdx.x, wid = tid >> 5, lane = tid & 31;
    int bm = blockIdx.y, bn = blockIdx.x;
    int wm = wid >> 2;        // 0..1 -> m offset wm*64
    int wn = wid & 3;         // 0..3 -> n offset wn*64

    float acc[4][8][4];
#pragma unroll
    for (int a = 0; a < 4; a++)
#pragma unroll
        for (int b = 0; b < 8; b++)
#pragma unroll
            for (int c = 0; c < 4; c++) acc[a][b][c] = 0.f;

    load_stage(sb, 0, Ah, Al, Bh, Bl, bm, bn, 0, tid); CP_COMMIT();
    load_stage(sb, 1, Ah, Al, Bh, Bl, bm, bn, 1, tid); CP_COMMIT();

    for (int kc = 0; kc < KT; kc++) {
        CP_WAIT(1);
        __syncthreads();
        if (kc + 2 < KT)
            load_stage(sb, (kc + 2) % 3, Ah, Al, Bh, Bl, bm, bn, kc + 2, tid);
        CP_COMMIT();

        uint32_t st = sb + (kc % 3) * STG_B;
#pragma unroll
        for (int ks = 0; ks < 2; ks++) {
            uint32_t bh[8][2], bl[8][2];
#pragma unroll
            for (int np = 0; np < 4; np++) {
                int r = wn * 64 + np * 16 + (lane & 7) + ((lane >> 4) & 1) * 8;
                int u = 2 * ks + ((lane >> 3) & 1);
                uint32_t ba = st + 2 * A_PL + swz(r, u);
                uint32_t t[4];
                ldsm4(t, ba);
                bh[np*2][0] = t[0]; bh[np*2][1] = t[1];
                bh[np*2+1][0] = t[2]; bh[np*2+1][1] = t[3];
                ldsm4(t, ba + B_PL);
                bl[np*2][0] = t[0]; bl[np*2][1] = t[1];
                bl[np*2+1][0] = t[2]; bl[np*2+1][1] = t[3];
            }
#pragma unroll
            for (int mt = 0; mt < 4; mt++) {
                int r = wm * 64 + mt * 16 + (lane & 15);
                int u = 2 * ks + (lane >> 4);
                uint32_t aa = st + swz(r, u);
                uint32_t ah[4], al[4];
                ldsm4(ah, aa);
                ldsm4(al, aa + A_PL);
#pragma unroll
                for (int nb = 0; nb < 8; nb++) {
                    mma16816(acc[mt][nb], ah, bh[nb]);
                    mma16816(acc[mt][nb], ah, bl[nb]);
                    mma16816(acc[mt][nb], al, bh[nb]);
                }
            }
        }
    }

#pragma unroll
    for (int mt = 0; mt < 4; mt++)
#pragma unroll
        for (int nb = 0; nb < 8; nb++) {
            float* c = acc[mt][nb];
            int row = bm * 128 + wm * 64 + mt * 16 + (lane >> 2);
            int col = bn * 256 + wn * 64 + nb * 8 + 2 * (lane & 3);
            *(float2*)(out + (size_t)row * ldc + col) = make_float2(c[0], c[1]);
            *(float2*)(out + (size_t)(row + 8) * ldc + col) = make_float2(c[2], c[3]);
        }
}

// ---------------------------------------------------------------------------
// QKNorm + partial 2D RoPE (unchanged)
// ---------------------------------------------------------------------------
__global__ __launch_bounds__(256)
void norm_rope2(const float* __restrict__ qw, const float* __restrict__ kw) {
    int vec = blockIdx.x * 8 + (threadIdx.x >> 5);
    int lane = threadIdx.x & 31;
    int hh = vec % (NH + NKV);
    int row = vec / (NH + NKV);
    bool is_q = hh < NH;
    int col = is_q ? hh * HD : GDIM + (hh - NH) * HD;
    float* p = g_qkv + (size_t)row * QKV_N + col;
    float v0 = p[lane], v1 = p[lane + 32];
    float sq = v0 * v0 + v1 * v1;
#pragma unroll
    for (int o = 16; o; o >>= 1) sq += __shfl_xor_sync(0xffffffffu, sq, o);
    float scl = rsqrtf(sq * (1.0f / HD) + 1e-6f);
    const float* wv = is_q ? qw : kw;
    v0 *= scl * wv[lane];
    v1 *= scl * wv[lane + 32];
    int s = row % SEQ;
    if (s < NZ) {
        int j = lane & 15;
        float pos = (lane < 16) ? (float)(s >> 4) : (float)(s & 15);
        float invf = __expf(-(float)j * 0.57564627324851142f);
        float c, sn;
        sincosf(pos * invf, &sn, &c);
        float o0 = v0 * c - v1 * sn;
        float o1 = v1 * c + v0 * sn;
        v0 = o0; v1 = o1;
    }
    p[lane] = v0;
    p[lane + 32] = v1;
}

// ---------------------------------------------------------------------------
// Flash-style mma attention (unchanged from round 4)
// ---------------------------------------------------------------------------
__device__ __forceinline__ void st_split4(char* hi, char* lo, float4 f) {
    uint32_t h0, l0, h1, l1;
    split2(f.x, f.y, h0, l0);
    split2(f.z, f.w, h1, l1);
    ((uint32_t*)hi)[0] = h0; ((uint32_t*)hi)[1] = h1;
    ((uint32_t*)lo)[0] = l0; ((uint32_t*)lo)[1] = l1;
}

__global__ __launch_bounds__(192, 1) void attn_mma() {
    extern __shared__ __align__(1024) char smem[];
    const int tid = threadIdx.x;
    const int mt = blockIdx.x, h = blockIdx.y, bt = blockIdx.z;
    const int m0 = (mt == 0) ? 0 : (mt == 1 ? 96 : 168);
    const int kvh = h >> 2;
    const float* gq = g_qkv + (size_t)bt * SEQ * QKV_N;
    const int kcol = GDIM + kvh * HD;
    const int vcol = GDIM + NKV * HD + kvh * HD;

    for (int idx = tid; idx < SEQ * 16; idx += 192) {
        int r = idx >> 4, u = idx & 15;
        const float* rp = gq + (size_t)r * QKV_N;
        float4 kk = *(const float4*)(rp + kcol + u * 4);
        float4 vv = *(const float4*)(rp + vcol + u * 4);
        int off = r * LDP + u * 8;
        st_split4(smem + SM_KHI + off, smem + SM_KLO + off, kk);
        st_split4(smem + SM_VHI + off, smem + SM_VLO + off, vv);
    }
    for (int idx = tid; idx < 96 * 16; idx += 192) {
        int r = idx >> 4, u = idx & 15;
        float4 qq = *(const float4*)(gq + (size_t)(m0 + r) * QKV_N + h * HD + u * 4);
        int off = r * LDP + u * 8;
        st_split4(smem + SM_QHI + off, smem + SM_QLO + off, qq);
    }
    for (int idx = tid; idx < 8 * 36; idx += 192) {
        int off = (SEQ + idx / 36) * LDP + (idx % 36) * 4;
        *(uint32_t*)(smem + SM_KHI + off) = 0;
        *(uint32_t*)(smem + SM_KLO + off) = 0;
        *(uint32_t*)(smem + SM_VHI + off) = 0;
        *(uint32_t*)(smem + SM_VLO + off) = 0;
    }
    __syncthreads();

    const uint32_t sb = smem_u32(smem);
    const int w = tid >> 5, lane = tid & 31;

    uint32_t qh[4][4], ql[4][4];
    {
        int r = w * 16 + (lane & 15);
        int uo = lane >> 4;
#pragma unroll
        for (int kc = 0; kc < 4; kc++) {
            uint32_t off = (uint32_t)(r * LDP + (2 * kc + uo) * 16);
            ldsm4(qh[kc], sb + SM_QHI + off);
            ldsm4(ql[kc], sb + SM_QLO + off);
        }
    }

    float oacc[8][4];
#pragma unroll
    for (int i = 0; i < 8; i++)
#pragma unroll
        for (int j = 0; j < 4; j++) oacc[i][j] = 0.f;
    float lsum0 = 0.f, lsum1 = 0.f;

    const int krow = (lane & 7) + ((lane >> 4) & 1) * 8;
    const int ku = (lane >> 3) & 1;
    const int vrow = (lane & 7) + ((lane >> 3) & 1) * 8;
    const int vu = (lane >> 4) & 1;

    for (int np = 0; np < 17; np++) {
        float sc[2][4] = {{0.f,0.f,0.f,0.f},{0.f,0.f,0.f,0.f}};
#pragma unroll
        for (int kc = 0; kc < 4; kc++) {
            uint32_t off = (uint32_t)((np * 16 + krow) * LDP + (2 * kc + ku) * 16);
            uint32_t bh[4], bl[4];
            ldsm4(bh, sb + SM_KHI + off);
            ldsm4(bl, sb + SM_KLO + off);
            mma16816(sc[0], qh[kc], bh);
            mma16816(sc[0], qh[kc], bl);
            mma16816(sc[0], ql[kc], bh);
            mma16816(sc[1], qh[kc], bh + 2);
            mma16816(sc[1], qh[kc], bl + 2);
            mma16816(sc[1], ql[kc], bh + 2);
        }
        float pf[2][4];
#pragma unroll
        for (int nb = 0; nb < 2; nb++)
#pragma unroll
            for (int e = 0; e < 4; e++) {
                float s = sc[nb][e] * 0.125f;
                float t = __expf(-0.04f * fabsf(s));
                float th = __fdividef(1.f - t, 1.f + t);
                float cap = (s >= 0.f) ? 50.f * th : -50.f * th;
                pf[nb][e] = __expf(cap);
            }
        if (np == 16) { pf[1][0] = pf[1][1] = pf[1][2] = pf[1][3] = 0.f; }
        lsum0 += pf[0][0] + pf[0][1] + pf[1][0] + pf[1][1];
        lsum1 += pf[0][2] + pf[0][3] + pf[1][2] + pf[1][3];

        uint32_t ph[4], pl[4];
        split2(pf[0][0], pf[0][1], ph[0], pl[0]);
        split2(pf[0][2], pf[0][3], ph[1], pl[1]);
        split2(pf[1][0], pf[1][1], ph[2], pl[2]);
        split2(pf[1][2], pf[1][3], ph[3], pl[3]);

#pragma unroll
        for (int db = 0; db < 4; db++) {
            uint32_t off = (uint32_t)((np * 16 + vrow) * LDP + (2 * db + vu) * 16);
            uint32_t vh[4], vl[4];
            ldsm4t(vh, sb + SM_VHI + off);
            ldsm4t(vl, sb + SM_VLO + off);
            mma16816(oacc[2*db],     ph, vh);
            mma16816(oacc[2*db],     ph, vl);
            mma16816(oacc[2*db],     pl, vh);
            mma16816(oacc[2*db+1],   ph, vh + 2);
            mma16816(oacc[2*db+1],   ph, vl + 2);
            mma16816(oacc[2*db+1],   pl, vh + 2);
        }
    }

    lsum0 += __shfl_xor_sync(0xffffffffu, lsum0, 1);
    lsum0 += __shfl_xor_sync(0xffffffffu, lsum0, 2);
    lsum1 += __shfl_xor_sync(0xffffffffu, lsum1, 1);
    lsum1 += __shfl_xor_sync(0xffffffffu, lsum1, 2);
    float inv0 = __fdividef(1.f, lsum0);
    float inv1 = __fdividef(1.f, lsum1);

    size_t row0 = (size_t)bt * SEQ + m0 + w * 16 + (lane >> 2);
    int colb = h * HD + 2 * (lane & 3);
#pragma unroll
    for (int nb = 0; nb < 8; nb++) {
        int col = colb + nb * 8;
        uint32_t hv, lv;
        split2(oacc[nb][0] * inv0, oacc[nb][1] * inv0, hv, lv);
        *(uint32_t*)(g_ahi + row0 * GDIM + col) = hv;
        *(uint32_t*)(g_alo + row0 * GDIM + col) = lv;
        split2(oacc[nb][2] * inv1, oacc[nb][3] * inv1, hv, lv);
        *(uint32_t*)(g_ahi + (row0 + 8) * GDIM + col) = hv;
        *(uint32_t*)(g_alo + (row0 + 8) * GDIM + col) = lv;
    }
}

// ---------------------------------------------------------------------------
extern "C" void kernel_launch(void* const* d_in, const int* in_sizes, int n_in,
                              void* d_out, int out_size) {
    const float* x   = (const float*)d_in[0];
    const float* wq  = (const float*)d_in[1];
    const float* wk  = (const float*)d_in[2];
    const float* wv  = (const float*)d_in[3];
    const float* wo  = (const float*)d_in[4];
    const float* qnw = (const float*)d_in[5];
    const float* knw = (const float*)d_in[6];
    float* out = (float*)d_out;

    __nv_bfloat16 *xhi, *xlo, *whi, *wlo, *wohi, *wolo, *ahi, *alo;
    float* qkv;
    cudaGetSymbolAddress((void**)&xhi, g_xhi);
    cudaGetSymbolAddress((void**)&xlo, g_xlo);
    cudaGetSymbolAddress((void**)&whi, g_whi);
    cudaGetSymbolAddress((void**)&wlo, g_wlo);
    cudaGetSymbolAddress((void**)&wohi, g_wohi);
    cudaGetSymbolAddress((void**)&wolo, g_wolo);
    cudaGetSymbolAddress((void**)&ahi, g_ahi);
    cudaGetSymbolAddress((void**)&alo, g_alo);
    cudaGetSymbolAddress((void**)&qkv, g_qkv);

    cudaFuncSetAttribute((const void*)gemm_mma,
                         cudaFuncAttributeMaxDynamicSharedMemorySize, GEMM_SMEM);
    cudaFuncSetAttribute((const void*)attn_mma,
                         cudaFuncAttributeMaxDynamicSharedMemorySize, ATT_SMEM);

    // 1) split operands into bf16 hi/lo planes
    split_rm<<<4224, 256>>>(x, xhi, xlo, MROWS * GDIM / 8);
    split_w_qkv<<<768, 256>>>(wq, wk, wv);
    split_rm<<<512, 256>>>(wo, wohi, wolo, GDIM * GDIM / 8);

    // 2) QKV projection (block 128x256)
    gemm_mma<<<dim3(QKV_N / 256, MROWS / 128), 256, GEMM_SMEM>>>(
        xhi, xlo, whi, wlo, qkv, QKV_N);

    // 3) QKNorm + 2D RoPE
    norm_rope2<<<(MROWS * (NH + NKV)) / 8, 256>>>(qnw, knw);

    // 4) tensor-core attention
    attn_mma<<<dim3(3, NH, BTN), 192, ATT_SMEM>>>();

    // 5) output projection
    gemm_mma<<<dim3(GDIM / 256, MROWS / 128), 256, GEMM_SMEM>>>(
        ahi, alo, wohi, wolo, out, GDIM);
}